// round 12
// baseline (speedup 1.0000x reference)
#include <cuda_runtime.h>
#include <cstdint>

// out[b,t,:] = ((vf[b] @ Wv + bv) @ Wp + bp), broadcast over t.
// (keys/values broadcast over T -> softmax uniform -> y == v; x/Wq/Wk drop out)
//
// Single persistent kernel, 128 blocks x 512 threads, ONE grid barrier.
// Block owns an 8-column stripe c0 = bid*8 of BOTH Wv and Wp (all 1024 k rows):
//   Phase A: stage Wv stripe -> smem transpose W_t[col][k]; compute
//            vv[b][c0+col] = bv + sum_k vf[b][k]*Wv[k][c0+col]  (in-block k
//            reduce: lane=(b,col), warp=64-k chunk, fixed-order 16-warp fold)
//            Wp stripe is LDG'd into regs BEFORE the barrier (latency hidden)
//   barrier (release/acquire, monotonic counter)
//   Phase B: same compute vs g_vv -> final r[b][c0+col]; broadcast the 8-col
//            stripe to all 4096 (b,t) rows (lane-paired 16B stores = full 32B
//            sectors). No partial matrices, no second barrier.
// All reductions fixed-order (deterministic).

#define C_     1024
#define B_     4
#define T_     1024
#define GRID_  128
#define BLOCK_ 512
#define NC_    8        // columns per block
#define WSP_   1028     // W_t row stride in floats (4-bank shift/col, 16B-aligned)

__device__ float g_vv[B_ * C_];     // 16 KB, final vv (L2-hot)
__device__ unsigned g_barcnt;       // monotonic across graph replays

__device__ __forceinline__ void grid_barrier() {
    __syncthreads();
    if (threadIdx.x == 0) {
        unsigned* ctr = &g_barcnt;
        unsigned old;
        asm volatile("atom.release.gpu.global.add.u32 %0, [%1], 1;"
                     : "=r"(old) : "l"(ctr) : "memory");
        const unsigned target = (old / GRID_ + 1u) * GRID_;
        unsigned cur;
        do {
            asm volatile("ld.acquire.gpu.global.u32 %0, [%1];"
                         : "=r"(cur) : "l"(ctr) : "memory");
        } while ((int)(cur - target) < 0);
    }
    __syncthreads();
}

__global__ void __launch_bounds__(BLOCK_, 1) ca_fused(
    const float* __restrict__ vf, const float* __restrict__ Wv,
    const float* __restrict__ bv, const float* __restrict__ Wp,
    const float* __restrict__ bp, float* __restrict__ out)
{
    __shared__ __align__(16) float W_t[NC_ * WSP_];   // 32.9 KB (reused A then B)
    __shared__ float s_part[16 * 32];                 // 2 KB
    __shared__ __align__(16) float s_r[32];           // final r stripe

    const int tid = threadIdx.x;
    const int bid = blockIdx.x;
    const int c0  = bid * NC_;
    const int w   = tid >> 5;          // k-chunk warp id (16)
    const int l   = tid & 31;          // lane = (b, col)
    const int bb  = l >> 3;
    const int col = l & 7;

    // ---- Stripe loads: Wv and Wp, 4 units of (row, half) per thread.
    // Warp covers 16 rows x 2 halves -> full 32B sectors (lane pairs). ----
    float4 wv[4], wp[4];
#pragma unroll
    for (int u = 0; u < 4; u++) {
        const int g = u * BLOCK_ + tid;
        const int row = g >> 1, half = g & 1;
        const size_t off = (size_t)row * C_ + c0 + half * 4;
        wv[u] = *(const float4*)(Wv + off);
        wp[u] = *(const float4*)(Wp + off);
    }
    float biasv = 0.f, biasp = 0.f;
    if (tid < 32) { biasv = bv[c0 + col]; biasp = bp[c0 + col]; }

    // ---- Scatter Wv -> W_t[col][k] (transpose; conflict-free STS) ----
#pragma unroll
    for (int u = 0; u < 4; u++) {
        const int g = u * BLOCK_ + tid;
        const int row = g >> 1, half = g & 1;
        W_t[(half * 4 + 0) * WSP_ + row] = wv[u].x;
        W_t[(half * 4 + 1) * WSP_ + row] = wv[u].y;
        W_t[(half * 4 + 2) * WSP_ + row] = wv[u].z;
        W_t[(half * 4 + 3) * WSP_ + row] = wv[u].w;
    }
    __syncthreads();

    // ---- Phase A compute: lane (b,col), warp's 64-k chunk, float4 steps ----
    float acc = 0.f;
    {
        const int kb = w * 64;
#pragma unroll
        for (int i = 0; i < 16; i++) {
            const int k = kb + i * 4;
            const float4 wt = *(const float4*)&W_t[col * WSP_ + k];
            const float4 a  = *(const float4*)&vf[bb * C_ + k];
            acc += wt.x * a.x + wt.y * a.y + wt.z * a.z + wt.w * a.w;
        }
    }
    s_part[w * 32 + l] = acc;
    __syncthreads();

    // warp 0 folds (fixed order) + writes final vv; others scatter Wp -> W_t
    if (tid < 32) {
        float s = biasv;
#pragma unroll
        for (int ww = 0; ww < 16; ww++) s += s_part[ww * 32 + l];
        g_vv[bb * C_ + c0 + col] = s;
    }
#pragma unroll
    for (int u = 0; u < 4; u++) {
        const int g = u * BLOCK_ + tid;
        const int row = g >> 1, half = g & 1;
        W_t[(half * 4 + 0) * WSP_ + row] = wp[u].x;
        W_t[(half * 4 + 1) * WSP_ + row] = wp[u].y;
        W_t[(half * 4 + 2) * WSP_ + row] = wp[u].z;
        W_t[(half * 4 + 3) * WSP_ + row] = wp[u].w;
    }

    grid_barrier();

    // ---- Phase B compute: r stripe vs g_vv (L2-hot, first touch here) ----
    acc = 0.f;
    {
        const int kb = w * 64;
#pragma unroll
        for (int i = 0; i < 16; i++) {
            const int k = kb + i * 4;
            const float4 wt = *(const float4*)&W_t[col * WSP_ + k];
            const float4 a  = *(const float4*)&g_vv[bb * C_ + k];
            acc += wt.x * a.x + wt.y * a.y + wt.z * a.z + wt.w * a.w;
        }
    }
    s_part[w * 32 + l] = acc;
    __syncthreads();
    if (tid < 32) {
        float s = biasp;
#pragma unroll
        for (int ww = 0; ww < 16; ww++) s += s_part[ww * 32 + l];
        s_r[l] = s;
    }
    __syncthreads();

    // ---- Broadcast: 8-col stripe to all 4096 (b,t) rows.
    // unit = (row, half); lane pairs give full 32B sectors. 16 STG.128/thread.
#pragma unroll
    for (int u = 0; u < 16; u++) {
        const int g = u * BLOCK_ + tid;
        const int row = g >> 1;            // 0..4095 = b*1024 + t
        const int half = g & 1;
        const int b = row >> 10;
        const float4 v = *(const float4*)&s_r[b * 8 + half * 4];
        *(float4*)&out[(size_t)row * C_ + c0 + half * 4] = v;
    }
}

// Inputs: 0 x, 1 vf, 2 Wq, 3 bq, 4 Wk, 5 bk, 6 Wv, 7 bv, 8 Wp, 9 bp
extern "C" void kernel_launch(void* const* d_in, const int* in_sizes, int n_in,
                              void* d_out, int out_size) {
    const float* vf = (const float*)d_in[1];
    const float* Wv = (const float*)d_in[6];
    const float* bv = (const float*)d_in[7];
    const float* Wp = (const float*)d_in[8];
    const float* bp = (const float*)d_in[9];
    float* out = (float*)d_out;

    ca_fused<<<GRID_, BLOCK_>>>(vf, Wv, bv, Wp, bp, out);
}